// round 14
// baseline (speedup 1.0000x reference)
#include <cuda_runtime.h>
#include <math.h>

#define NS    16
#define D128  128
#define MARGIN 0.8f
#define EPS   1e-6f
#define GRID  592
#define KH    32
#define PIT   36
#define MAXB  8192
#define MAXT  8512
#define PADSQ 1.0e30f

__device__ float g_sq[MAXB];
__device__ int   g_order[MAXB];
__device__ int   g_bhist[32][NS];
__device__ int4  g_tiles[MAXT];
__device__ int   g_T;
__device__ unsigned long long g_bestP[MAXB];
__device__ unsigned long long g_bestN[MAXB];
__device__ float g_bL[GRID], g_bV[GRID];
__device__ unsigned g_arrive;
__device__ unsigned g_epoch;

__device__ __forceinline__ unsigned mono(float f) {
    unsigned u = __float_as_uint(f);
    return (u & 0x80000000u) ? ~u : (u | 0x80000000u);
}
#define FMA2(d, a, b) asm("fma.rn.f32x2 %0, %1, %2, %0;" : "+l"(d) : "l"(a), "l"(b))
#define SWZ(x) ((((x) >> 1) & 7) << 2)
#define CP16(dst, src) asm volatile("cp.async.ca.shared.global [%0], [%1], 16;" :: "r"(dst), "l"(src))
#define CPCOMMIT() asm volatile("cp.async.commit_group;" ::: "memory")
#define CPWAIT0()  asm volatile("cp.async.wait_group 0;" ::: "memory")

__global__ void __launch_bounds__(256, 4) k_all(const float* __restrict__ emb,
                                                const int* __restrict__ labels,
                                                const int* __restrict__ sbj,
                                                float* __restrict__ out, int B) {
    __shared__ __align__(16) float As[2][64 * PIT];
    __shared__ __align__(16) float Bs[2][64 * PIT];
    __shared__ int   aId[64], aLab[64], bId[64], bLab[64];
    __shared__ float aSq[64], bSq[64];
    __shared__ unsigned long long sPb[64], sNb[64];
    __shared__ int whist[8][NS], woff[8][NS];
    __shared__ int sbase[NS + 1], stot[NS], boffs[NS];
    __shared__ int tb[NS], tn[NS];
    __shared__ float rl[256], rv[256];
    __shared__ float sL[8], sV[8];
    __shared__ unsigned sE0;

    const int tid = threadIdx.x;
    const int w = tid >> 5, lane = tid & 31;
    const int bx = blockIdx.x;
    const unsigned full = 0xffffffffu;
    const int NC = (B + 255) >> 8;
    unsigned nbar = 1;

    if (tid == 0) sE0 = *(volatile unsigned*)&g_epoch;
    __syncthreads();

    #define GBAR() do { \
        __syncthreads(); \
        if (tid == 0) { \
            __threadfence(); \
            unsigned old = atomicAdd(&g_arrive, 1u); \
            if (old == GRID - 1) { g_arrive = 0; __threadfence(); atomicAdd(&g_epoch, 1u); } \
            while (*(volatile unsigned*)&g_epoch - sE0 < nbar) { } \
            __threadfence(); \
        } \
        __syncthreads(); \
        nbar++; \
    } while (0)

    // ---------- phase 0: init bests + row norms + per-chunk histogram/ranks ----------
    for (int i = bx * 256 + tid; i < B; i += GRID * 256) { g_bestP[i] = 0ULL; g_bestN[i] = 0ULL; }
    for (int i = bx * 8 + w; i < B; i += GRID * 8) {
        const float4 v = reinterpret_cast<const float4*>(emb + (size_t)i * D128)[lane];
        float s = v.x * v.x + v.y * v.y + v.z * v.z + v.w * v.w;
        #pragma unroll
        for (int off = 16; off > 0; off >>= 1) s += __shfl_xor_sync(full, s, off);
        if (lane == 0) g_sq[i] = s;
    }
    int myRank = 0, myS = NS;
    if (bx < NC) {
        int i = bx * 256 + tid;
        if (i < B) { myS = sbj[i]; myS = min(max(myS, 0), NS - 1); }
        unsigned myMask = 0u; int cnt = 0;
        #pragma unroll
        for (int t2 = 0; t2 < NS; t2++) {
            unsigned m = __ballot_sync(full, myS == t2);
            if (myS == t2) myMask = m;
            if (lane == t2) cnt = __popc(m);
        }
        int rIW = __popc(myMask & ((1u << lane) - 1u));
        if (lane < NS) whist[w][lane] = cnt;
        __syncthreads();
        if (tid < NS) {
            int acc = 0;
            #pragma unroll
            for (int w2 = 0; w2 < 8; w2++) { woff[w2][tid] = acc; acc += whist[w2][tid]; }
            g_bhist[bx][tid] = acc;
        }
        __syncthreads();
        if (i < B && myS < NS) myRank = woff[w][myS] + rIW;
    }
    GBAR();

    // ---------- phase 1: global scan + scatter + tile list ----------
    if (bx < NC) {
        if (tid < NS) {
            int acc = 0, myoff = 0;
            for (int b = 0; b < NC; b++) { if (b == bx) myoff = acc; acc += g_bhist[b][tid]; }
            boffs[tid] = myoff; stot[tid] = acc;
        }
        __syncthreads();
        if (tid == 0) {
            int a = 0;
            for (int s = 0; s < NS; s++) { sbase[s] = a; a += stot[s]; }
            sbase[NS] = a;
        }
        __syncthreads();
        int i = bx * 256 + tid;
        if (i < B && myS < NS)
            g_order[sbase[myS] + boffs[myS] + myRank] = i;
        if (bx == 0) {
            if (tid == 0) {
                int acc = 0;
                for (int s = 0; s < NS; s++) {
                    int len = sbase[s + 1] - sbase[s];
                    int m = (len + 63) >> 6;
                    tb[s] = acc; tn[s] = m;
                    acc += m * (m + 1) / 2;
                }
                g_T = acc;
            }
            __syncthreads();
            for (int s = w; s < NS; s += 8) {
                int m = tn[s], lo = sbase[s], hi = sbase[s + 1];
                int ntri = m * (m + 1) / 2;
                for (int t = lane; t < ntri; t += 32) {
                    int a2 = 0, rem = t;
                    while (rem >= m - a2) { rem -= m - a2; a2++; }
                    int b2 = a2 + rem;
                    g_tiles[tb[s] + t] = make_int4(lo + 64 * a2, lo + 64 * b2, hi, 0);
                }
            }
        }
    }
    GBAR();

    // ---------- phase 2: mining (64x64 tiles, cp.async ping-pong, k-packed FMA2) ----------
    {
        const int tx = tid & 15, ty = tid >> 4;
        const int T = g_T;
        for (int t = bx; t < T; t += GRID) {
            const int4 dsc = g_tiles[t];
            const int aBase = dsc.x, bBase = dsc.y, hi = dsc.z;
            const int na = min(64, hi - aBase);
            const int nb = min(64, hi - bBase);

            __syncthreads();   // previous tile fully consumed
            if (tid < 64) {
                if (tid < na) { int i = g_order[aBase + tid]; aId[tid] = i; aLab[tid] = labels[i]; aSq[tid] = g_sq[i]; }
                else { aId[tid] = -1; aLab[tid] = -2; aSq[tid] = PADSQ; }
            } else if (tid < 128) {
                int c = tid - 64;
                if (c < nb) { int j = g_order[bBase + c]; bId[c] = j; bLab[c] = labels[j]; bSq[c] = g_sq[j]; }
                else { bId[c] = -1; bLab[c] = -3; bSq[c] = PADSQ; }
            } else if (tid < 192) {
                sPb[tid - 128] = 0ULL;
            } else {
                sNb[tid - 192] = 0ULL;
            }
            __syncthreads();   // meta ready for cp.async addressing

            // fill helper mapping: idx = tid + 256*i → side/row/kq
            #define FILL(KHOFF, BUF) do { \
                _Pragma("unroll") \
                for (int i2 = 0; i2 < 4; i2++) { \
                    int idx = tid + (i2 << 8); \
                    int side = idx >> 9, rem = idx & 511; \
                    int row = rem & 63, kq = rem >> 6; \
                    int id = side ? bId[row] : aId[row]; \
                    const float* src = emb + (size_t)max(id, 0) * D128 + (KHOFF) + kq * 4; \
                    float* dstf = (side ? &Bs[BUF][0] : &As[BUF][0]) + row * PIT + ((kq * 4) ^ SWZ(row)); \
                    unsigned dsm = (unsigned)__cvta_generic_to_shared(dstf); \
                    CP16(dsm, src); \
                } \
                CPCOMMIT(); \
            } while (0)

            FILL(0, 0);

            unsigned long long acc2[4][4];
            #pragma unroll
            for (int r = 0; r < 4; r++)
                #pragma unroll
                for (int c = 0; c < 4; c++) acc2[r][c] = 0ULL;

            #pragma unroll
            for (int ch = 0; ch < 4; ch++) {
                const int p = ch & 1;
                CPWAIT0();          // chunk ch landed (this thread's copies)
                __syncthreads();    // visible to all; compute(ch-1) done by all
                if (ch < 3) FILL((ch + 1) * KH, 1 - p);

                #pragma unroll
                for (int kb = 0; kb < KH; kb += 4) {
                    ulonglong2 Ar[4], Bc[4];
                    #pragma unroll
                    for (int q = 0; q < 4; q++) {
                        int rr = ty + 16 * q;
                        int cc = tx + 16 * q;
                        Ar[q] = *reinterpret_cast<const ulonglong2*>(&As[p][rr * PIT + (kb ^ SWZ(rr))]);
                        Bc[q] = *reinterpret_cast<const ulonglong2*>(&Bs[p][cc * PIT + (kb ^ SWZ(cc))]);
                    }
                    #pragma unroll
                    for (int r = 0; r < 4; r++)
                        #pragma unroll
                        for (int c = 0; c < 4; c++) {
                            FMA2(acc2[r][c], Ar[r].x, Bc[c].x);
                            FMA2(acc2[r][c], Ar[r].y, Bc[c].y);
                        }
                }
            }

            // selection: rows rr = ty+16q, cols cc = tx+16q; dot = lo+hi
            int myBI[4], myBL[4]; float myBS[4];
            #pragma unroll
            for (int q = 0; q < 4; q++) {
                int cc = tx + 16 * q;
                myBI[q] = bId[cc]; myBL[q] = bLab[cc]; myBS[q] = bSq[cc];
            }
            unsigned long long colP[4], colN[4];
            #pragma unroll
            for (int q = 0; q < 4; q++) { colP[q] = 0ULL; colN[q] = 0ULL; }

            #pragma unroll
            for (int r = 0; r < 4; r++) {
                int rr = ty + 16 * r;
                int aI = aId[rr], aL = aLab[rr];
                float aS = aSq[rr];
                unsigned long long rowP = 0ULL, rowN = 0ULL;
                #pragma unroll
                for (int c = 0; c < 4; c++) {
                    float lo, hie;
                    asm("mov.b64 {%0,%1}, %2;" : "=f"(lo), "=f"(hie) : "l"(acc2[r][c]));
                    float d2 = aS + myBS[c] - 2.f * (lo + hie);
                    unsigned m = mono(d2);
                    if (aL == myBL[c]) {
                        if (aI != myBI[c]) {
                            unsigned long long kr = ((unsigned long long)m << 32) | (unsigned)(~myBI[c]);
                            unsigned long long kc = ((unsigned long long)m << 32) | (unsigned)(~aI);
                            if (kr > rowP) rowP = kr;
                            if (kc > colP[c]) colP[c] = kc;
                        }
                    } else {
                        unsigned long long kr = ((unsigned long long)(~m) << 32) | (unsigned)(~myBI[c]);
                        unsigned long long kc = ((unsigned long long)(~m) << 32) | (unsigned)(~aI);
                        if (kr > rowN) rowN = kr;
                        if (kc > colN[c]) colN[c] = kc;
                    }
                }
                // reduce across 16 tx (within half-warp)
                #pragma unroll
                for (int off = 1; off < 16; off <<= 1) {
                    unsigned long long oP = __shfl_xor_sync(full, rowP, off);
                    unsigned long long oN = __shfl_xor_sync(full, rowN, off);
                    if (oP > rowP) rowP = oP;
                    if (oN > rowN) rowN = oN;
                }
                if (tx == 0 && aI >= 0) {
                    if (rowP) atomicMax(&g_bestP[aI], rowP);
                    if (rowN) atomicMax(&g_bestN[aI], rowN);
                }
            }
            // col-side: combine the two ty-parities in warp, then smem atomics
            #pragma unroll
            for (int q = 0; q < 4; q++) {
                unsigned long long oP = __shfl_xor_sync(full, colP[q], 16);
                unsigned long long oN = __shfl_xor_sync(full, colN[q], 16);
                if (oP > colP[q]) colP[q] = oP;
                if (oN > colN[q]) colN[q] = oN;
            }
            if (lane < 16) {
                #pragma unroll
                for (int q = 0; q < 4; q++) {
                    int cc = tx + 16 * q;
                    if (colP[q]) atomicMax(&sPb[cc], colP[q]);
                    if (colN[q]) atomicMax(&sNb[cc], colN[q]);
                }
            }
            __syncthreads();
            if (tid < 64) {
                int j = bId[tid];
                if (j >= 0) {
                    if (sPb[tid]) atomicMax(&g_bestP[j], sPb[tid]);
                    if (sNb[tid]) atomicMax(&g_bestN[j], sNb[tid]);
                }
            }
            #undef FILL
        }
    }
    GBAR();

    // ---------- phase 3: decode + triplet epilogue (all warps) ----------
    {
        float accL = 0.f, accV = 0.f;
        for (int i = bx * 8 + w; i < B; i += GRID * 8) {
            unsigned long long kp = g_bestP[i];
            unsigned long long kn = g_bestN[i];
            int bpI = kp ? (int)(~(unsigned)kp) : -1;
            int bnI = kn ? (int)(~(unsigned)kn) : -1;
            if (bpI >= 0 && bnI >= 0) {
                const float4 a = reinterpret_cast<const float4*>(emb + (size_t)i   * D128)[lane];
                const float4 p = reinterpret_cast<const float4*>(emb + (size_t)bpI * D128)[lane];
                const float4 n = reinterpret_cast<const float4*>(emb + (size_t)bnI * D128)[lane];
                float dx, sp, sn;
                dx = a.x - p.x + EPS; sp = dx * dx;
                dx = a.y - p.y + EPS; sp = fmaf(dx, dx, sp);
                dx = a.z - p.z + EPS; sp = fmaf(dx, dx, sp);
                dx = a.w - p.w + EPS; sp = fmaf(dx, dx, sp);
                dx = a.x - n.x + EPS; sn = dx * dx;
                dx = a.y - n.y + EPS; sn = fmaf(dx, dx, sn);
                dx = a.z - n.z + EPS; sn = fmaf(dx, dx, sn);
                dx = a.w - n.w + EPS; sn = fmaf(dx, dx, sn);
                #pragma unroll
                for (int off = 16; off > 0; off >>= 1) {
                    sp += __shfl_xor_sync(full, sp, off);
                    sn += __shfl_xor_sync(full, sn, off);
                }
                accL += fmaxf(sqrtf(sp) - sqrtf(sn) + MARGIN, 0.f);
                accV += 1.f;
            }
        }
        if (lane == 0) { sL[w] = accL; sV[w] = accV; }
        __syncthreads();
        if (tid == 0) {
            float l = 0.f, v = 0.f;
            #pragma unroll
            for (int q = 0; q < 8; q++) { l += sL[q]; v += sV[q]; }
            g_bL[bx] = l; g_bV[bx] = v;
        }
    }
    GBAR();

    // ---------- phase 4: final deterministic reduction (block 0) ----------
    if (bx == 0) {
        float l = 0.f, v = 0.f;
        for (int b = tid; b < GRID; b += 256) { l += g_bL[b]; v += g_bV[b]; }
        rl[tid] = l; rv[tid] = v;
        __syncthreads();
        for (int off = 128; off > 0; off >>= 1) {
            if (tid < off) { rl[tid] += rl[tid + off]; rv[tid] += rv[tid + off]; }
            __syncthreads();
        }
        if (tid == 0) {
            float cnt = rv[0];
            out[0] = (cnt > 0.f) ? (rl[0] / fmaxf(cnt, 1.f)) : 0.f;
        }
    }
}

extern "C" void kernel_launch(void* const* d_in, const int* in_sizes, int n_in,
                              void* d_out, int out_size) {
    const float* emb   = (const float*)d_in[0];
    const int* labels  = (const int*)d_in[1];
    const int* sbj     = (const int*)d_in[2];
    float* out = (float*)d_out;
    int B = in_sizes[1];

    k_all<<<GRID, 256>>>(emb, labels, sbj, out, B);
}

// round 15
// speedup vs baseline: 1.4954x; 1.4954x over previous
#include <cuda_runtime.h>
#include <math.h>

#define NS    16
#define D128  128
#define MARGIN 0.8f
#define EPS   1e-6f
#define GRID  592
#define KH    64
#define AP    68
#define MAXB  8192
#define MAXT  8512
#define PADSQ 1.0e30f

__device__ float g_sq[MAXB];
__device__ int   g_order[MAXB];
__device__ int   g_bhist[32][NS];
__device__ int4  g_tiles[MAXT];
__device__ int   g_T;
__device__ unsigned long long g_bestP[MAXB];
__device__ unsigned long long g_bestN[MAXB];
__device__ float g_bL[GRID], g_bV[GRID];
__device__ unsigned g_arrive;
__device__ unsigned g_epoch;

__device__ __forceinline__ unsigned mono(float f) {
    unsigned u = __float_as_uint(f);
    return (u & 0x80000000u) ? ~u : (u | 0x80000000u);
}
__device__ __forceinline__ unsigned long long dup2(float a) {
    unsigned long long d;
    asm("mov.b64 %0, {%1, %1};" : "=l"(d) : "f"(a));
    return d;
}
#define FMA2(d, a, b) asm("fma.rn.f32x2 %0, %1, %2, %0;" : "+l"(d) : "l"(a), "l"(b))

__global__ void __launch_bounds__(256, 4) k_all(const float* __restrict__ emb,
                                                const int* __restrict__ labels,
                                                const int* __restrict__ sbj,
                                                float* __restrict__ out, int B) {
    __shared__ __align__(16) float As[KH * AP];
    __shared__ __align__(16) float Bs[KH * AP];
    __shared__ int   aId[64], aLab[64], bId[64], bLab[64];
    __shared__ float aSq[64], bSq[64];
    __shared__ unsigned long long sPb[64], sNb[64];
    __shared__ int whist[8][NS], woff[8][NS];
    __shared__ int sbase[NS + 1], stot[NS], boffs[NS];
    __shared__ int tb[NS], tn[NS];
    __shared__ float rl[256], rv[256];
    __shared__ float sL[8], sV[8];
    __shared__ unsigned sE0;

    const int tid = threadIdx.x;
    const int w = tid >> 5, lane = tid & 31;
    const int bx = blockIdx.x;
    const unsigned full = 0xffffffffu;
    const int NC = (B + 255) >> 8;
    unsigned nbar = 1;

    if (tid == 0) sE0 = *(volatile unsigned*)&g_epoch;
    __syncthreads();

    #define GBAR() do { \
        __syncthreads(); \
        if (tid == 0) { \
            __threadfence(); \
            unsigned old = atomicAdd(&g_arrive, 1u); \
            if (old == GRID - 1) { g_arrive = 0; __threadfence(); atomicAdd(&g_epoch, 1u); } \
            while (*(volatile unsigned*)&g_epoch - sE0 < nbar) { } \
            __threadfence(); \
        } \
        __syncthreads(); \
        nbar++; \
    } while (0)

    // ---------- phase 0: init bests + row norms + per-chunk histogram/ranks ----------
    for (int i = bx * 256 + tid; i < B; i += GRID * 256) { g_bestP[i] = 0ULL; g_bestN[i] = 0ULL; }
    for (int i = bx * 8 + w; i < B; i += GRID * 8) {
        const float4 v = reinterpret_cast<const float4*>(emb + (size_t)i * D128)[lane];
        float s = v.x * v.x + v.y * v.y + v.z * v.z + v.w * v.w;
        #pragma unroll
        for (int off = 16; off > 0; off >>= 1) s += __shfl_xor_sync(full, s, off);
        if (lane == 0) g_sq[i] = s;
    }
    int myRank = 0, myS = NS;
    if (bx < NC) {
        int i = bx * 256 + tid;
        if (i < B) { myS = sbj[i]; myS = min(max(myS, 0), NS - 1); }
        unsigned myMask = 0u; int cnt = 0;
        #pragma unroll
        for (int t2 = 0; t2 < NS; t2++) {
            unsigned m = __ballot_sync(full, myS == t2);
            if (myS == t2) myMask = m;
            if (lane == t2) cnt = __popc(m);
        }
        int rIW = __popc(myMask & ((1u << lane) - 1u));
        if (lane < NS) whist[w][lane] = cnt;
        __syncthreads();
        if (tid < NS) {
            int acc = 0;
            #pragma unroll
            for (int w2 = 0; w2 < 8; w2++) { woff[w2][tid] = acc; acc += whist[w2][tid]; }
            g_bhist[bx][tid] = acc;
        }
        __syncthreads();
        if (i < B && myS < NS) myRank = woff[w][myS] + rIW;
    }
    GBAR();

    // ---------- phase 1: global scan + scatter + tile list ----------
    if (bx < NC) {
        if (tid < NS) {
            int acc = 0, myoff = 0;
            for (int b = 0; b < NC; b++) { if (b == bx) myoff = acc; acc += g_bhist[b][tid]; }
            boffs[tid] = myoff; stot[tid] = acc;
        }
        __syncthreads();
        if (tid == 0) {
            int a = 0;
            for (int s = 0; s < NS; s++) { sbase[s] = a; a += stot[s]; }
            sbase[NS] = a;
        }
        __syncthreads();
        int i = bx * 256 + tid;
        if (i < B && myS < NS)
            g_order[sbase[myS] + boffs[myS] + myRank] = i;
        if (bx == 0) {
            if (tid == 0) {
                int acc = 0;
                for (int s = 0; s < NS; s++) {
                    int len = sbase[s + 1] - sbase[s];
                    int m = (len + 63) >> 6;
                    tb[s] = acc; tn[s] = m;
                    acc += m * (m + 1) / 2;
                }
                g_T = acc;
            }
            __syncthreads();
            for (int s = w; s < NS; s += 8) {
                int m = tn[s], lo = sbase[s], hi = sbase[s + 1];
                int ntri = m * (m + 1) / 2;
                for (int t = lane; t < ntri; t += 32) {
                    int a2 = 0, rem = t;
                    while (rem >= m - a2) { rem -= m - a2; a2++; }
                    int b2 = a2 + rem;
                    g_tiles[tb[s] + t] = make_int4(lo + 64 * a2, lo + 64 * b2, hi, 0);
                }
            }
        }
    }
    GBAR();

    // ---------- phase 2: mining (64x64 tiles, full triangle) ----------
    {
        const int tx = tid & 15, ty = tid >> 4;
        const int T = g_T;
        for (int t = bx; t < T; t += GRID) {
            const int4 dsc = g_tiles[t];
            const int aBase = dsc.x, bBase = dsc.y, hi = dsc.z;
            const int na = min(64, hi - aBase);
            const int nb = min(64, hi - bBase);

            __syncthreads();   // previous tile fully consumed
            if (tid < 64) {
                if (tid < na) { int i = g_order[aBase + tid]; aId[tid] = i; aLab[tid] = labels[i]; aSq[tid] = g_sq[i]; }
                else { aId[tid] = -1; aLab[tid] = -2; aSq[tid] = PADSQ; }
            } else if (tid < 128) {
                int c = tid - 64;
                if (c < nb) { int j = g_order[bBase + c]; bId[c] = j; bLab[c] = labels[j]; bSq[c] = g_sq[j]; }
                else { bId[c] = -1; bLab[c] = -3; bSq[c] = PADSQ; }
            } else if (tid < 192) {
                sPb[tid - 128] = 0ULL;
            } else {
                sNb[tid - 192] = 0ULL;
            }

            unsigned long long acc2[4][2];
            #pragma unroll
            for (int r = 0; r < 4; r++) { acc2[r][0] = 0ULL; acc2[r][1] = 0ULL; }

            for (int kh = 0; kh < D128; kh += KH) {
                __syncthreads();   // meta ready / prior chunk consumed
                // fill: lanes vary row (conflict-free scalar stores); kq = float4 idx 0..15
                #pragma unroll
                for (int it = 0; it < 4; it++) {
                    int idx = tid + it * 256;
                    int r = idx & 63, kq = idx >> 6;
                    float4 v = make_float4(0.f, 0.f, 0.f, 0.f);
                    float4 u = make_float4(0.f, 0.f, 0.f, 0.f);
                    int ia = aId[r], ib = bId[r];
                    if (ia >= 0) v = reinterpret_cast<const float4*>(emb + (size_t)ia * D128 + kh)[kq];
                    if (ib >= 0) u = reinterpret_cast<const float4*>(emb + (size_t)ib * D128 + kh)[kq];
                    int kb = kq * 4;
                    As[(kb + 0) * AP + r] = v.x;
                    As[(kb + 1) * AP + r] = v.y;
                    As[(kb + 2) * AP + r] = v.z;
                    As[(kb + 3) * AP + r] = v.w;
                    Bs[(kb + 0) * AP + r] = u.x;
                    Bs[(kb + 1) * AP + r] = u.y;
                    Bs[(kb + 2) * AP + r] = u.z;
                    Bs[(kb + 3) * AP + r] = u.w;
                }
                __syncthreads();

                #pragma unroll 8
                for (int k = 0; k < KH; k++) {
                    const float4 a0 = *reinterpret_cast<const float4*>(&As[k * AP + 4 * ty]);
                    const ulonglong2 bq = *reinterpret_cast<const ulonglong2*>(&Bs[k * AP + 4 * tx]);
                    unsigned long long aa0 = dup2(a0.x), aa1 = dup2(a0.y);
                    unsigned long long aa2 = dup2(a0.z), aa3 = dup2(a0.w);
                    FMA2(acc2[0][0], aa0, bq.x); FMA2(acc2[0][1], aa0, bq.y);
                    FMA2(acc2[1][0], aa1, bq.x); FMA2(acc2[1][1], aa1, bq.y);
                    FMA2(acc2[2][0], aa2, bq.x); FMA2(acc2[2][1], aa2, bq.y);
                    FMA2(acc2[3][0], aa3, bq.x); FMA2(acc2[3][1], aa3, bq.y);
                }
            }
            __syncthreads();   // compute done before selection reads meta

            int myBI[4], myBL[4]; float myBS[4];
            #pragma unroll
            for (int q = 0; q < 4; q++) {
                int cc = 4 * tx + q;
                myBI[q] = bId[cc]; myBL[q] = bLab[cc]; myBS[q] = bSq[cc];
            }
            unsigned long long colP[4], colN[4];
            #pragma unroll
            for (int q = 0; q < 4; q++) { colP[q] = 0ULL; colN[q] = 0ULL; }

            #pragma unroll
            for (int r = 0; r < 4; r++) {
                int rr = 4 * ty + r;
                int aI = aId[rr], aL = aLab[rr];
                float aS = aSq[rr];
                float af[2];
                unsigned long long rowP = 0ULL, rowN = 0ULL;
                #pragma unroll
                for (int p = 0; p < 2; p++) {
                    asm("mov.b64 {%0,%1}, %2;" : "=f"(af[0]), "=f"(af[1]) : "l"(acc2[r][p]));
                    #pragma unroll
                    for (int j = 0; j < 2; j++) {
                        int c = 2 * p + j;
                        float d2 = aS + myBS[c] - 2.f * af[j];
                        unsigned m = mono(d2);
                        if (aL == myBL[c]) {
                            if (aI != myBI[c]) {
                                unsigned long long kr = ((unsigned long long)m << 32) | (unsigned)(~myBI[c]);
                                unsigned long long kc = ((unsigned long long)m << 32) | (unsigned)(~aI);
                                if (kr > rowP) rowP = kr;
                                if (kc > colP[c]) colP[c] = kc;
                            }
                        } else {
                            unsigned long long kr = ((unsigned long long)(~m) << 32) | (unsigned)(~myBI[c]);
                            unsigned long long kc = ((unsigned long long)(~m) << 32) | (unsigned)(~aI);
                            if (kr > rowN) rowN = kr;
                            if (kc > colN[c]) colN[c] = kc;
                        }
                    }
                }
                // reduce across 16 tx (stays within half-warp)
                #pragma unroll
                for (int off = 1; off < 16; off <<= 1) {
                    unsigned long long oP = __shfl_xor_sync(full, rowP, off);
                    unsigned long long oN = __shfl_xor_sync(full, rowN, off);
                    if (oP > rowP) rowP = oP;
                    if (oN > rowN) rowN = oN;
                }
                if (tx == 0 && aI >= 0) {
                    if (rowP) atomicMax(&g_bestP[aI], rowP);
                    if (rowN) atomicMax(&g_bestN[aI], rowN);
                }
            }
            // col-side: combine the two ty values in this warp, then smem atomics
            #pragma unroll
            for (int q = 0; q < 4; q++) {
                unsigned long long oP = __shfl_xor_sync(full, colP[q], 16);
                unsigned long long oN = __shfl_xor_sync(full, colN[q], 16);
                if (oP > colP[q]) colP[q] = oP;
                if (oN > colN[q]) colN[q] = oN;
            }
            if (lane < 16) {
                #pragma unroll
                for (int q = 0; q < 4; q++) {
                    int cc = 4 * tx + q;
                    if (colP[q]) atomicMax(&sPb[cc], colP[q]);
                    if (colN[q]) atomicMax(&sNb[cc], colN[q]);
                }
            }
            __syncthreads();
            if (tid < 64) {
                int j = bId[tid];
                if (j >= 0) {
                    if (sPb[tid]) atomicMax(&g_bestP[j], sPb[tid]);
                    if (sNb[tid]) atomicMax(&g_bestN[j], sNb[tid]);
                }
            }
        }
    }
    GBAR();

    // ---------- phase 3: decode + triplet epilogue (all warps) ----------
    {
        float accL = 0.f, accV = 0.f;
        for (int i = bx * 8 + w; i < B; i += GRID * 8) {
            unsigned long long kp = g_bestP[i];
            unsigned long long kn = g_bestN[i];
            int bpI = kp ? (int)(~(unsigned)kp) : -1;
            int bnI = kn ? (int)(~(unsigned)kn) : -1;
            if (bpI >= 0 && bnI >= 0) {
                const float4 a = reinterpret_cast<const float4*>(emb + (size_t)i   * D128)[lane];
                const float4 p = reinterpret_cast<const float4*>(emb + (size_t)bpI * D128)[lane];
                const float4 n = reinterpret_cast<const float4*>(emb + (size_t)bnI * D128)[lane];
                float dx, sp, sn;
                dx = a.x - p.x + EPS; sp = dx * dx;
                dx = a.y - p.y + EPS; sp = fmaf(dx, dx, sp);
                dx = a.z - p.z + EPS; sp = fmaf(dx, dx, sp);
                dx = a.w - p.w + EPS; sp = fmaf(dx, dx, sp);
                dx = a.x - n.x + EPS; sn = dx * dx;
                dx = a.y - n.y + EPS; sn = fmaf(dx, dx, sn);
                dx = a.z - n.z + EPS; sn = fmaf(dx, dx, sn);
                dx = a.w - n.w + EPS; sn = fmaf(dx, dx, sn);
                #pragma unroll
                for (int off = 16; off > 0; off >>= 1) {
                    sp += __shfl_xor_sync(full, sp, off);
                    sn += __shfl_xor_sync(full, sn, off);
                }
                accL += fmaxf(sqrtf(sp) - sqrtf(sn) + MARGIN, 0.f);
                accV += 1.f;
            }
        }
        if (lane == 0) { sL[w] = accL; sV[w] = accV; }
        __syncthreads();
        if (tid == 0) {
            float l = 0.f, v = 0.f;
            #pragma unroll
            for (int q = 0; q < 8; q++) { l += sL[q]; v += sV[q]; }
            g_bL[bx] = l; g_bV[bx] = v;
        }
    }
    GBAR();

    // ---------- phase 4: final deterministic reduction (block 0) ----------
    if (bx == 0) {
        float l = 0.f, v = 0.f;
        for (int b = tid; b < GRID; b += 256) { l += g_bL[b]; v += g_bV[b]; }
        rl[tid] = l; rv[tid] = v;
        __syncthreads();
        for (int off = 128; off > 0; off >>= 1) {
            if (tid < off) { rl[tid] += rl[tid + off]; rv[tid] += rv[tid + off]; }
            __syncthreads();
        }
        if (tid == 0) {
            float cnt = rv[0];
            out[0] = (cnt > 0.f) ? (rl[0] / fmaxf(cnt, 1.f)) : 0.f;
        }
    }
}

extern "C" void kernel_launch(void* const* d_in, const int* in_sizes, int n_in,
                              void* d_out, int out_size) {
    const float* emb   = (const float*)d_in[0];
    const int* labels  = (const int*)d_in[1];
    const int* sbj     = (const int*)d_in[2];
    float* out = (float*)d_out;
    int B = in_sizes[1];

    k_all<<<GRID, 256>>>(emb, labels, sbj, out, B);
}